// round 1
// baseline (speedup 1.0000x reference)
#include <cuda_runtime.h>
#include <float.h>

// And_Convolution: out[n][s] = min_{k<16} ( in[n][4*s + k] * w[k] )
// N=1024, L=8192, KERNEL=16, STRIDE=4 -> OUTW = (L-16)/4 + 1 = 2045
//
// STRIDE==4 => every window start is float4-aligned. View the row as 2048
// float4s; window s covers float4 indices [s, s+4). Each thread computes
// T=8 consecutive outputs from T+3=11 float4 loads (register blocking).

#define ROW_L      8192
#define ROW_L4     2048      // float4s per row
#define OUTW       2045      // outputs per row
#define TPB        256
#define TOUT       8         // outputs per thread: 256*8 = 2048 >= 2045

__global__ __launch_bounds__(TPB)
void and_conv_kernel(const float4* __restrict__ in,
                     const float*  __restrict__ w,
                     float*        __restrict__ out)
{
    const int row = blockIdx.x;
    const int t   = threadIdx.x;

    // Broadcast-load the 16 weights as 4 float4s (all threads same addr -> bcast)
    const float4* __restrict__ w4 = reinterpret_cast<const float4*>(w);
    float4 wv0 = __ldg(&w4[0]);
    float4 wv1 = __ldg(&w4[1]);
    float4 wv2 = __ldg(&w4[2]);
    float4 wv3 = __ldg(&w4[3]);

    const float4* __restrict__ rowp = in + (size_t)row * ROW_L4;
    const int base = t * TOUT;   // first float4 index / first output index

    float acc[TOUT];
#pragma unroll
    for (int i = 0; i < TOUT; ++i) acc[i] = FLT_MAX;

#pragma unroll
    for (int j = 0; j < TOUT + 3; ++j) {
        const int idx = base + j;
        float4 v;
        if (idx < ROW_L4) {
            v = __ldg(&rowp[idx]);
        } else {
            v = make_float4(FLT_MAX, FLT_MAX, FLT_MAX, FLT_MAX);
        }

        // float4 at window-relative position dj contributes min4(v * w4[dj])
        // to output s = j - dj.
#pragma unroll
        for (int dj = 0; dj < 4; ++dj) {
            const int s = j - dj;
            if (s >= 0 && s < TOUT) {
                float4 wv;
                if      (dj == 0) wv = wv0;
                else if (dj == 1) wv = wv1;
                else if (dj == 2) wv = wv2;
                else              wv = wv3;
                float m = fminf(fminf(v.x * wv.x, v.y * wv.y),
                                fminf(v.z * wv.z, v.w * wv.w));
                acc[s] = fminf(acc[s], m);
            }
        }
    }

    float* __restrict__ orow = out + (size_t)row * OUTW;
#pragma unroll
    for (int i = 0; i < TOUT; ++i) {
        const int s = base + i;
        if (s < OUTW) orow[s] = acc[i];
    }
}

extern "C" void kernel_launch(void* const* d_in, const int* in_sizes, int n_in,
                              void* d_out, int out_size)
{
    const float* inp = (const float*)d_in[0];   // (N, 8192) fp32
    const float* w   = (const float*)d_in[1];   // (1, 16)   fp32

    const int N = in_sizes[0] / ROW_L;          // 1024

    and_conv_kernel<<<N, TPB>>>(reinterpret_cast<const float4*>(inp), w,
                                (float*)d_out);
}

// round 2
// speedup vs baseline: 1.4267x; 1.4267x over previous
#include <cuda_runtime.h>
#include <float.h>

// And_Convolution: out[n][s] = min_{k<16} ( in[n][4*s + k] * w[k] )
// N=1024, L=8192, KERNEL=16, STRIDE=4 -> OUTW = (L-16)/4 + 1 = 2045
//
// STRIDE==4 => every window start is float4-aligned. View the row as 2048
// float4s; window s covers float4 indices [s, s+4).
//
// Round-2 change: explicit two-phase structure. Phase 1 issues ALL 11
// LDG.E.128 back-to-back into a register array (MLP=11, hides ~250cy L2
// latency). Phase 2 computes. Per-load predication replaced by index
// clamping: clamped loads read valid in-row data and only feed outputs
// s >= OUTW, which are never stored.

#define ROW_L      8192
#define ROW_L4     2048      // float4s per row
#define OUTW       2045      // outputs per row
#define TPB        256
#define TOUT       8         // outputs per thread: 256*8 = 2048 >= 2045
#define NLD        (TOUT + 3)

__global__ __launch_bounds__(TPB, 3)
void and_conv_kernel(const float4* __restrict__ in,
                     const float*  __restrict__ w,
                     float*        __restrict__ out)
{
    const int row  = blockIdx.x;
    const int t    = threadIdx.x;
    const int base = t * TOUT;   // first float4 index / first output index

    const float4* __restrict__ rowp = in + (size_t)row * ROW_L4;

    // ---- Phase 1: issue all input loads back-to-back (MLP = 11) ----
    float4 v[NLD];
#pragma unroll
    for (int j = 0; j < NLD; ++j) {
        int idx = base + j;
        idx = idx < (ROW_L4 - 1) ? idx : (ROW_L4 - 1);   // clamp, no predication
        v[j] = __ldg(&rowp[idx]);
    }

    // Broadcast-load the 16 weights as 4 float4s (uniform addr -> broadcast)
    const float4* __restrict__ w4 = reinterpret_cast<const float4*>(w);
    const float4 wv0 = __ldg(&w4[0]);
    const float4 wv1 = __ldg(&w4[1]);
    const float4 wv2 = __ldg(&w4[2]);
    const float4 wv3 = __ldg(&w4[3]);

    // ---- Phase 2: compute 8 outputs ----
    float acc[TOUT];
#pragma unroll
    for (int s = 0; s < TOUT; ++s) {
        float4 a = v[s + 0];
        float4 b = v[s + 1];
        float4 c = v[s + 2];
        float4 d = v[s + 3];
        float m0 = fminf(fminf(a.x * wv0.x, a.y * wv0.y),
                         fminf(a.z * wv0.z, a.w * wv0.w));
        float m1 = fminf(fminf(b.x * wv1.x, b.y * wv1.y),
                         fminf(b.z * wv1.z, b.w * wv1.w));
        float m2 = fminf(fminf(c.x * wv2.x, c.y * wv2.y),
                         fminf(c.z * wv2.z, c.w * wv2.w));
        float m3 = fminf(fminf(d.x * wv3.x, d.y * wv3.y),
                         fminf(d.z * wv3.z, d.w * wv3.w));
        acc[s] = fminf(fminf(m0, m1), fminf(m2, m3));
    }

    // ---- Phase 3: store (row base is only 4B-aligned: OUTW*4 = 8180B) ----
    float* __restrict__ orow = out + (size_t)row * OUTW;
    if (base + TOUT <= OUTW) {
#pragma unroll
        for (int i = 0; i < TOUT; ++i) orow[base + i] = acc[i];
    } else {
#pragma unroll
        for (int i = 0; i < TOUT; ++i) {
            if (base + i < OUTW) orow[base + i] = acc[i];
        }
    }
}

extern "C" void kernel_launch(void* const* d_in, const int* in_sizes, int n_in,
                              void* d_out, int out_size)
{
    const float* inp = (const float*)d_in[0];   // (N, 8192) fp32
    const float* w   = (const float*)d_in[1];   // (1, 16)   fp32

    const int N = in_sizes[0] / ROW_L;          // 1024

    and_conv_kernel<<<N, TPB>>>(reinterpret_cast<const float4*>(inp), w,
                                (float*)d_out);
}

// round 3
// speedup vs baseline: 1.8448x; 1.2931x over previous
#include <cuda_runtime.h>
#include <float.h>

// And_Convolution: out[n][s] = min_{k<16} ( in[n][4*s + k] * w[k] )
// N=1024, L=8192, KERNEL=16, STRIDE=4 -> OUTW = (L-16)/4 + 1 = 2045
//
// Decomposition: window s covers float4 indices u = s+d (d=0..3).
//   g_d(u) = min_{c<4} in4[u].c * w[4d+c]
//   out[s] = min( g0(s), g1(s+1), g2(s+2), g3(s+3) )
//
// Round-3: one output per lane. Lane t loads float4 s=base+t (fully
// coalesced: 4 L1 lines / warp instead of 32), computes g0..g3 locally,
// and fetches neighbors' g1/g2/g3 via shfl_down. Lanes 29-31 patch the
// cross-warp halo with tiny predicated loads (L1-hit from next warp's data).

#define ROW_L       8192
#define ROW_L4      2048     // float4s per row
#define OUTW        2045     // outputs per row
#define TPB         256
#define CTAS_PER_ROW 8       // 8 * 256 = 2048 lanes >= 2045 outputs

__device__ __forceinline__ float min4w(float4 v, float4 w) {
    return fminf(fminf(v.x * w.x, v.y * w.y),
                 fminf(v.z * w.z, v.w * w.w));
}

__global__ __launch_bounds__(TPB)
void and_conv_kernel(const float4* __restrict__ in,
                     const float*  __restrict__ w,
                     float*        __restrict__ out)
{
    const int row   = blockIdx.x >> 3;        // / CTAS_PER_ROW
    const int chunk = blockIdx.x & 7;
    const int lane  = threadIdx.x & 31;
    const int s     = chunk * TPB + threadIdx.x;   // output idx == float4 idx

    const float4* __restrict__ rowp = in + (size_t)row * ROW_L4;

    // Coalesced main load (clamp: clamped lanes only feed outputs >= OUTW)
    const int idx = s < (ROW_L4 - 1) ? s : (ROW_L4 - 1);
    const float4 v = __ldg(&rowp[idx]);

    // Broadcast weights (uniform address -> broadcast, L1-resident)
    const float4* __restrict__ w4 = reinterpret_cast<const float4*>(w);
    const float4 wv0 = __ldg(&w4[0]);
    const float4 wv1 = __ldg(&w4[1]);
    const float4 wv2 = __ldg(&w4[2]);
    const float4 wv3 = __ldg(&w4[3]);

    // Partial mins for this float4 at each window-relative position
    const float g0 = min4w(v, wv0);
    const float g1 = min4w(v, wv1);
    const float g2 = min4w(v, wv2);
    const float g3 = min4w(v, wv3);

    // Pull neighbors' partials
    float n1 = __shfl_down_sync(0xFFFFFFFFu, g1, 1);
    float n2 = __shfl_down_sync(0xFFFFFFFFu, g2, 2);
    float n3 = __shfl_down_sync(0xFFFFFFFFu, g3, 3);

    // Cross-warp halo: lanes 29..31 fetch what shfl couldn't provide.
    if (lane + 3 > 31) {   // lane 29,30,31
        if (lane + 1 > 31) {   // lane 31
            int i1 = (s + 1) < (ROW_L4 - 1) ? (s + 1) : (ROW_L4 - 1);
            n1 = min4w(__ldg(&rowp[i1]), wv1);
        }
        if (lane + 2 > 31) {   // lane 30,31
            int i2 = (s + 2) < (ROW_L4 - 1) ? (s + 2) : (ROW_L4 - 1);
            n2 = min4w(__ldg(&rowp[i2]), wv2);
        }
        {                      // lane 29,30,31
            int i3 = (s + 3) < (ROW_L4 - 1) ? (s + 3) : (ROW_L4 - 1);
            n3 = min4w(__ldg(&rowp[i3]), wv3);
        }
    }

    const float r = fminf(fminf(g0, n1), fminf(n2, n3));

    if (s < OUTW) out[(size_t)row * OUTW + s] = r;
}

extern "C" void kernel_launch(void* const* d_in, const int* in_sizes, int n_in,
                              void* d_out, int out_size)
{
    const float* inp = (const float*)d_in[0];   // (N, 8192) fp32
    const float* w   = (const float*)d_in[1];   // (1, 16)   fp32

    const int N = in_sizes[0] / ROW_L;          // 1024

    and_conv_kernel<<<N * CTAS_PER_ROW, TPB>>>(
        reinterpret_cast<const float4*>(inp), w, (float*)d_out);
}

// round 4
// speedup vs baseline: 2.4956x; 1.3528x over previous
#include <cuda_runtime.h>
#include <float.h>

// And_Convolution: out[n][s] = min_{k<16} ( in[n][4*s + k] * w[k] )
// N=1024, L=8192, KERNEL=16, STRIDE=4 -> OUTW = (L-16)/4 + 1 = 2045
//
// Decomposition: window s covers float4 indices u = s+d (d=0..3):
//   g_d(u) = min_c in4[u].c * w[4d+c];  out[s] = min_d g_d(s+d)
//
// Round-4: 4 output groups per warp. Lane t owns float4s wbase+32i+t
// (i=0..3, coalesced) plus one halo float4 wbase+128+t (clamped).
// Group i's lanes 29-31 need g_d of float4s wbase+32(i+1)+{0..2} ==
// group i+1 lanes 0-2 --> resolved with broadcast shuffles from the
// next group's registers. No divergent patch loads, MLP=5 per thread.

#define ROW_L4   2048
#define OUTW     2045
#define TPB      256
#define GROUPS   4
#define WARP_OUT (32 * GROUPS)           // 128 outputs per warp
#define CTA_OUT  (TPB / 32 * WARP_OUT)   // 1024 outputs per CTA
#define CTAS_PER_ROW 2                   // 2048 >= 2045

__device__ __forceinline__ float min4w(float4 v, float4 w) {
    return fminf(fminf(v.x * w.x, v.y * w.y),
                 fminf(v.z * w.z, v.w * w.w));
}

__global__ __launch_bounds__(TPB)
void and_conv_kernel(const float4* __restrict__ in,
                     const float*  __restrict__ w,
                     float*        __restrict__ out)
{
    const int row   = blockIdx.x >> 1;
    const int chunk = blockIdx.x & 1;
    const int warp  = threadIdx.x >> 5;
    const int lane  = threadIdx.x & 31;
    const int wbase = chunk * CTA_OUT + warp * WARP_OUT;  // warp's first output

    const float4* __restrict__ rowp = in + (size_t)row * ROW_L4;

    // ---- Phase 1: all loads back-to-back (MLP = 5, fully coalesced) ----
    float4 v[GROUPS + 1];
#pragma unroll
    for (int i = 0; i < GROUPS; ++i)
        v[i] = __ldg(&rowp[wbase + 32 * i + lane]);       // always in-bounds
    {
        int idx = wbase + 32 * GROUPS + lane;             // halo (clamp)
        v[GROUPS] = __ldg(&rowp[idx < ROW_L4 - 1 ? idx : ROW_L4 - 1]);
    }

    const float4* __restrict__ w4 = reinterpret_cast<const float4*>(w);
    const float4 wv0 = __ldg(&w4[0]);
    const float4 wv1 = __ldg(&w4[1]);
    const float4 wv2 = __ldg(&w4[2]);
    const float4 wv3 = __ldg(&w4[3]);

    // ---- Phase 2: partial mins ----
    float g0[GROUPS], g1[GROUPS + 1], g2[GROUPS + 1], g3[GROUPS + 1];
#pragma unroll
    for (int i = 0; i < GROUPS; ++i) g0[i] = min4w(v[i], wv0);
#pragma unroll
    for (int i = 0; i <= GROUPS; ++i) {
        g1[i] = min4w(v[i], wv1);
        g2[i] = min4w(v[i], wv2);
        g3[i] = min4w(v[i], wv3);
    }

    // ---- Phase 3: assemble outputs via shuffles ----
    const unsigned F = 0xFFFFFFFFu;
    float* __restrict__ orow = out + (size_t)row * OUTW;
#pragma unroll
    for (int i = 0; i < GROUPS; ++i) {
        float a1 = __shfl_down_sync(F, g1[i], 1);
        float a2 = __shfl_down_sync(F, g2[i], 2);
        float a3 = __shfl_down_sync(F, g3[i], 3);
        float b1 = __shfl_sync(F, g1[i + 1], 0);
        float b2 = __shfl_sync(F, g2[i + 1], (lane - 30) & 31);
        float b3 = __shfl_sync(F, g3[i + 1], (lane - 29) & 31);

        float n1 = (lane == 31) ? b1 : a1;
        float n2 = (lane >= 30) ? b2 : a2;
        float n3 = (lane >= 29) ? b3 : a3;

        float r = fminf(fminf(g0[i], n1), fminf(n2, n3));

        int s = wbase + 32 * i + lane;
        if (s < OUTW) orow[s] = r;
    }
}

extern "C" void kernel_launch(void* const* d_in, const int* in_sizes, int n_in,
                              void* d_out, int out_size)
{
    const float* inp = (const float*)d_in[0];   // (N, 8192) fp32
    const float* w   = (const float*)d_in[1];   // (1, 16)   fp32

    const int N = in_sizes[0] / 8192;           // 1024

    and_conv_kernel<<<N * CTAS_PER_ROW, TPB>>>(
        reinterpret_cast<const float4*>(inp), w, (float*)d_out);
}

// round 5
// speedup vs baseline: 3.0681x; 1.2294x over previous
#include <cuda_runtime.h>
#include <float.h>

// And_Convolution: out[n][s] = min_{k<16} ( in[n][4*s + k] * w[k] )
// N=1024, L=8192, KERNEL=16, STRIDE=4 -> OUTW = (L-16)/4 + 1 = 2045
//
// Decomposition: window s covers float4 indices u = s+d (d=0..3):
//   g_d(u) = min_c in4[u].c * w[4d+c];  out[s] = min_d g_d(s+d)
//
// Round-5: 8 output groups per warp, 1 CTA per row (8 warps * 256 = 2048).
// MLP = 9 coalesced float4 loads per lane. Cross-lane assembly uses ONE
// shuffle per shift: the lanes whose read wraps (dest 32-d..31 <- src
// 0..d-1) need group i+1's value, so the SOURCE lane pre-selects
// g[i+1] when lane < d, then a single index-shuffle serves everyone.

#define ROW_L4   2048
#define OUTW     2045
#define TPB      256
#define GROUPS   8
#define WARP_OUT (32 * GROUPS)           // 256 outputs per warp

__device__ __forceinline__ float min4w(float4 v, float4 w) {
    return fminf(fminf(v.x * w.x, v.y * w.y),
                 fminf(v.z * w.z, v.w * w.w));
}

__global__ __launch_bounds__(TPB)
void and_conv_kernel(const float4* __restrict__ in,
                     const float*  __restrict__ w,
                     float*        __restrict__ out)
{
    const int row   = blockIdx.x;
    const int warp  = threadIdx.x >> 5;
    const int lane  = threadIdx.x & 31;
    const int wbase = warp * WARP_OUT;            // warp's first output / float4

    const float4* __restrict__ rowp = in + (size_t)row * ROW_L4;

    // ---- Phase 1: all loads back-to-back (MLP = 9, fully coalesced) ----
    float4 v[GROUPS + 1];
#pragma unroll
    for (int i = 0; i < GROUPS; ++i)
        v[i] = __ldg(&rowp[wbase + 32 * i + lane]);       // always in-bounds
    {
        int idx = wbase + 32 * GROUPS + lane;             // halo (clamp)
        v[GROUPS] = __ldg(&rowp[idx < ROW_L4 - 1 ? idx : ROW_L4 - 1]);
    }

    const float4* __restrict__ w4 = reinterpret_cast<const float4*>(w);
    const float4 wv0 = __ldg(&w4[0]);
    const float4 wv1 = __ldg(&w4[1]);
    const float4 wv2 = __ldg(&w4[2]);
    const float4 wv3 = __ldg(&w4[3]);

    // ---- Phase 2: partial mins ----
    float g0[GROUPS], g1[GROUPS + 1], g2[GROUPS + 1], g3[GROUPS + 1];
#pragma unroll
    for (int i = 0; i < GROUPS; ++i) g0[i] = min4w(v[i], wv0);
#pragma unroll
    for (int i = 0; i <= GROUPS; ++i) {
        g1[i] = min4w(v[i], wv1);
        g2[i] = min4w(v[i], wv2);
        g3[i] = min4w(v[i], wv3);
    }

    // ---- Phase 3: assemble via 3 shuffles per group ----
    const unsigned F = 0xFFFFFFFFu;
    float* __restrict__ orow = out + (size_t)row * OUTW;
#pragma unroll
    for (int i = 0; i < GROUPS; ++i) {
        // Source-side select: wrapped readers (dest lane >= 32-d) hit
        // src lanes 0..d-1, which must supply group i+1's partial.
        float t1 = (lane < 1) ? g1[i + 1] : g1[i];
        float t2 = (lane < 2) ? g2[i + 1] : g2[i];
        float t3 = (lane < 3) ? g3[i + 1] : g3[i];
        float n1 = __shfl_sync(F, t1, (lane + 1) & 31);
        float n2 = __shfl_sync(F, t2, (lane + 2) & 31);
        float n3 = __shfl_sync(F, t3, (lane + 3) & 31);

        float r = fminf(fminf(g0[i], n1), fminf(n2, n3));

        int s = wbase + 32 * i + lane;
        if (s < OUTW) orow[s] = r;
    }
}

extern "C" void kernel_launch(void* const* d_in, const int* in_sizes, int n_in,
                              void* d_out, int out_size)
{
    const float* inp = (const float*)d_in[0];   // (N, 8192) fp32
    const float* w   = (const float*)d_in[1];   // (1, 16)   fp32

    const int N = in_sizes[0] / 8192;           // 1024

    and_conv_kernel<<<N, TPB>>>(
        reinterpret_cast<const float4*>(inp), w, (float*)d_out);
}

// round 6
// speedup vs baseline: 3.0791x; 1.0036x over previous
#include <cuda_runtime.h>
#include <float.h>

// And_Convolution: out[n][s] = min_{k<16} ( in[n][4*s + k] * w[k] )
// N=1024, L=8192, KERNEL=16, STRIDE=4 -> OUTW = (L-16)/4 + 1 = 2045
//
// Decomposition: window s covers float4 indices u = s+d (d=0..3):
//   g_d(u) = min_c in4[u].c * w[4d+c];  out[s] = min_d g_d(s+d)
//
// Round-6: same warp-level algorithm as R5 (8 groups/warp, MLP=9,
// source-side-select + single index-shuffle per shift), but CTA shrunk
// to 128 threads / 1024 outputs, 2 CTAs per row, grid = 2048.
// Rationale: R5's 1024x256 launch yielded 1.38 waves at 5 CTAs/SM with a
// 38%-full second wave. 128-thread CTAs allow ~11 CTAs/SM -> ~1.26 waves
// with much finer work-steal granularity and more interleaved warps to
// cover memory latency.

#define ROW_L4   2048
#define OUTW     2045
#define TPB      128
#define GROUPS   8
#define WARP_OUT (32 * GROUPS)            // 256 outputs per warp
#define CTA_OUT  ((TPB / 32) * WARP_OUT)  // 1024 outputs per CTA
#define CTAS_PER_ROW 2

__device__ __forceinline__ float min4w(float4 v, float4 w) {
    return fminf(fminf(v.x * w.x, v.y * w.y),
                 fminf(v.z * w.z, v.w * w.w));
}

__global__ __launch_bounds__(TPB)
void and_conv_kernel(const float4* __restrict__ in,
                     const float*  __restrict__ w,
                     float*        __restrict__ out)
{
    const int row   = blockIdx.x >> 1;
    const int chunk = blockIdx.x & 1;
    const int warp  = threadIdx.x >> 5;
    const int lane  = threadIdx.x & 31;
    const int wbase = chunk * CTA_OUT + warp * WARP_OUT;  // first output/float4

    const float4* __restrict__ rowp = in + (size_t)row * ROW_L4;

    // ---- Phase 1: all loads back-to-back (MLP = 9, fully coalesced) ----
    float4 v[GROUPS + 1];
#pragma unroll
    for (int i = 0; i < GROUPS; ++i)
        v[i] = __ldg(&rowp[wbase + 32 * i + lane]);       // always in-bounds
    {
        int idx = wbase + 32 * GROUPS + lane;             // halo (clamp)
        v[GROUPS] = __ldg(&rowp[idx < ROW_L4 - 1 ? idx : ROW_L4 - 1]);
    }

    const float4* __restrict__ w4 = reinterpret_cast<const float4*>(w);
    const float4 wv0 = __ldg(&w4[0]);
    const float4 wv1 = __ldg(&w4[1]);
    const float4 wv2 = __ldg(&w4[2]);
    const float4 wv3 = __ldg(&w4[3]);

    // ---- Phase 2: partial mins ----
    float g0[GROUPS], g1[GROUPS + 1], g2[GROUPS + 1], g3[GROUPS + 1];
#pragma unroll
    for (int i = 0; i < GROUPS; ++i) g0[i] = min4w(v[i], wv0);
#pragma unroll
    for (int i = 0; i <= GROUPS; ++i) {
        g1[i] = min4w(v[i], wv1);
        g2[i] = min4w(v[i], wv2);
        g3[i] = min4w(v[i], wv3);
    }

    // ---- Phase 3: assemble via 3 shuffles per group ----
    const unsigned F = 0xFFFFFFFFu;
    float* __restrict__ orow = out + (size_t)row * OUTW;
#pragma unroll
    for (int i = 0; i < GROUPS; ++i) {
        // Wrapped readers (dest lane >= 32-d) hit src lanes 0..d-1, which
        // must supply group i+1's partial -> source-side select.
        float t1 = (lane < 1) ? g1[i + 1] : g1[i];
        float t2 = (lane < 2) ? g2[i + 1] : g2[i];
        float t3 = (lane < 3) ? g3[i + 1] : g3[i];
        float n1 = __shfl_sync(F, t1, (lane + 1) & 31);
        float n2 = __shfl_sync(F, t2, (lane + 2) & 31);
        float n3 = __shfl_sync(F, t3, (lane + 3) & 31);

        float r = fminf(fminf(g0[i], n1), fminf(n2, n3));

        int s = wbase + 32 * i + lane;
        if (s < OUTW) orow[s] = r;
    }
}

extern "C" void kernel_launch(void* const* d_in, const int* in_sizes, int n_in,
                              void* d_out, int out_size)
{
    const float* inp = (const float*)d_in[0];   // (N, 8192) fp32
    const float* w   = (const float*)d_in[1];   // (1, 16)   fp32

    const int N = in_sizes[0] / 8192;           // 1024

    and_conv_kernel<<<N * CTAS_PER_ROW, TPB>>>(
        reinterpret_cast<const float4*>(inp), w, (float*)d_out);
}

// round 7
// speedup vs baseline: 3.1704x; 1.0296x over previous
#include <cuda_runtime.h>
#include <float.h>

// And_Convolution: out[n][s] = min_{k<16} ( in[n][4*s + k] * w[k] )
// N=1024, L=8192, KERNEL=16, STRIDE=4 -> OUTW = (L-16)/4 + 1 = 2045
//
// Decomposition: window s covers float4 indices u = s+d (d=0..3):
//   g_d(u) = min_c in4[u].c * w[4d+c];  out[s] = min_d g_d(s+d)
//
// Round-7: identical geometry to the 8.9us kernel (128 thr, 8 groups/warp,
// MLP=9, source-side-select + 1 shuffle per shift). Change: the weighted
// min4 now uses packed mul.rn.f32x2 (Blackwell FFMA/FMUL2 path) -> 2 MUL2
// + 3 FMNMX instead of 4 FMUL + 3 FMNMX. ~22% fewer issue slots; kernel
// was shown to be instruction/dependency bound (all mem bars <= 41%).

#define ROW_L4   2048
#define OUTW     2045
#define TPB      128
#define GROUPS   8
#define WARP_OUT (32 * GROUPS)            // 256 outputs per warp
#define CTA_OUT  ((TPB / 32) * WARP_OUT)  // 1024 outputs per CTA
#define CTAS_PER_ROW 2

typedef unsigned long long u64;

__device__ __forceinline__ u64 pk2(float a, float b) {
    u64 r;
    asm("mov.b64 %0, {%1, %2};" : "=l"(r) : "f"(a), "f"(b));
    return r;
}
__device__ __forceinline__ u64 mul2(u64 a, u64 b) {
    u64 r;
    asm("mul.rn.f32x2 %0, %1, %2;" : "=l"(r) : "l"(a), "l"(b));
    return r;
}
__device__ __forceinline__ float2 upk2(u64 p) {
    float x, y;
    asm("mov.b64 {%0, %1}, %2;" : "=f"(x), "=f"(y) : "l"(p));
    return make_float2(x, y);
}

// min over 4 components of v*w, with v,w pre-packed as (lo=xy, hi=zw)
__device__ __forceinline__ float min4w_p(u64 vlo, u64 vhi, u64 wlo, u64 whi) {
    float2 a = upk2(mul2(vlo, wlo));
    float2 b = upk2(mul2(vhi, whi));
    return fminf(fminf(a.x, b.x), fminf(a.y, b.y));
}

__global__ __launch_bounds__(TPB)
void and_conv_kernel(const float4* __restrict__ in,
                     const float*  __restrict__ w,
                     float*        __restrict__ out)
{
    const int row   = blockIdx.x >> 1;
    const int chunk = blockIdx.x & 1;
    const int warp  = threadIdx.x >> 5;
    const int lane  = threadIdx.x & 31;
    const int wbase = chunk * CTA_OUT + warp * WARP_OUT;  // first output/float4

    const float4* __restrict__ rowp = in + (size_t)row * ROW_L4;

    // ---- Phase 1: all loads back-to-back (MLP = 9, fully coalesced) ----
    float4 v[GROUPS + 1];
#pragma unroll
    for (int i = 0; i < GROUPS; ++i)
        v[i] = __ldg(&rowp[wbase + 32 * i + lane]);       // always in-bounds
    {
        int idx = wbase + 32 * GROUPS + lane;             // halo (clamp)
        v[GROUPS] = __ldg(&rowp[idx < ROW_L4 - 1 ? idx : ROW_L4 - 1]);
    }

    // Weights, packed into f32x2 pairs (uniform -> broadcast, reg-resident)
    const float4* __restrict__ w4 = reinterpret_cast<const float4*>(w);
    u64 wlo[4], whi[4];
#pragma unroll
    for (int d = 0; d < 4; ++d) {
        float4 wd = __ldg(&w4[d]);
        wlo[d] = pk2(wd.x, wd.y);
        whi[d] = pk2(wd.z, wd.w);
    }

    // ---- Phase 2: partial mins (packed multiplies) ----
    float g0[GROUPS], g1[GROUPS + 1], g2[GROUPS + 1], g3[GROUPS + 1];
#pragma unroll
    for (int i = 0; i <= GROUPS; ++i) {
        const u64 vlo = pk2(v[i].x, v[i].y);   // free: LDG.128 pairs adjacent
        const u64 vhi = pk2(v[i].z, v[i].w);
        if (i < GROUPS) g0[i] = min4w_p(vlo, vhi, wlo[0], whi[0]);
        g1[i] = min4w_p(vlo, vhi, wlo[1], whi[1]);
        g2[i] = min4w_p(vlo, vhi, wlo[2], whi[2]);
        g3[i] = min4w_p(vlo, vhi, wlo[3], whi[3]);
    }

    // ---- Phase 3: assemble via 3 shuffles per group ----
    const unsigned F = 0xFFFFFFFFu;
    float* __restrict__ orow = out + (size_t)row * OUTW;
#pragma unroll
    for (int i = 0; i < GROUPS; ++i) {
        // Wrapped readers (dest lane >= 32-d) hit src lanes 0..d-1, which
        // must supply group i+1's partial -> source-side select.
        float t1 = (lane < 1) ? g1[i + 1] : g1[i];
        float t2 = (lane < 2) ? g2[i + 1] : g2[i];
        float t3 = (lane < 3) ? g3[i + 1] : g3[i];
        float n1 = __shfl_sync(F, t1, (lane + 1) & 31);
        float n2 = __shfl_sync(F, t2, (lane + 2) & 31);
        float n3 = __shfl_sync(F, t3, (lane + 3) & 31);

        float r = fminf(fminf(g0[i], n1), fminf(n2, n3));

        int s = wbase + 32 * i + lane;
        if (s < OUTW) orow[s] = r;
    }
}

extern "C" void kernel_launch(void* const* d_in, const int* in_sizes, int n_in,
                              void* d_out, int out_size)
{
    const float* inp = (const float*)d_in[0];   // (N, 8192) fp32
    const float* w   = (const float*)d_in[1];   // (1, 16)   fp32

    const int N = in_sizes[0] / 8192;           // 1024

    and_conv_kernel<<<N * CTAS_PER_ROW, TPB>>>(
        reinterpret_cast<const float4*>(inp), w, (float*)d_out);
}